// round 13
// baseline (speedup 1.0000x reference)
#include <cuda_runtime.h>
#include <cuda_bf16.h>
#include <math.h>

// ---------------- problem constants ----------------
#define Bv   2
#define Sv   2048
#define Ev   768
#define Hv   12
#define Dv   64
#define TBv  128
#define Mv   (Bv*Sv)      // 4096
#define BHv  (Bv*Hv)      // 24

// ---------------- scratch (device globals; no allocation at runtime) ------
__device__ float g_q  [BHv * Sv * Dv];   // [b,h,s,d]
__device__ float g_k  [BHv * Sv * Dv];
__device__ float g_v  [BHv * Sv * Dv];
__device__ float g_ctx[BHv * Sv * Dv];
__device__ float g_tb [BHv];

// ---------------- task-bias projection: tb[b,h] = task_bias[b,:] . Wtb[h,:] + btb[h]
__global__ void tb_kernel(const float* __restrict__ task_bias,
                          const float* __restrict__ Wtb,
                          const float* __restrict__ btb) {
    int i = threadIdx.x;
    if (i < BHv) {
        int b = i / Hv, h = i % Hv;
        float s = btb[h];
        const float* tbp = task_bias + b * TBv;
        const float* wp  = Wtb + h * TBv;
        #pragma unroll 8
        for (int t = 0; t < TBv; t++) s += tbp[t] * wp[t];
        g_tb[i] = s;
    }
}

// ---------------- QKV projection GEMM -------------------------------------
// C = X @ W^T + bias ; X [4096,768], W [768,768] row-major (W[n][k]).
// Output scattered into head layout g_{q,k,v}[((b*H+h)*S+s)*D + d].
__global__ __launch_bounds__(256)
void proj_kernel(const float* __restrict__ X, const float* __restrict__ W,
                 const float* __restrict__ bias, int which) {
    __shared__ float As[16][65];
    __shared__ float Ws[16][65];
    const int t    = threadIdx.x;
    const int lrow = t >> 2;            // 0..63
    const int lcol = (t & 3) << 2;      // 0,4,8,12
    const int tx   = t & 15;
    const int ty   = t >> 4;
    const int m0   = blockIdx.y * 64;
    const int n0   = blockIdx.x * 64;

    const float* xrow = X + (size_t)(m0 + lrow) * Ev;
    const float* wrow = W + (size_t)(n0 + lrow) * Ev;

    float acc[4][4] = {};
    for (int kt = 0; kt < Ev / 16; kt++) {
        int k = kt * 16 + lcol;
        float4 xa = *(const float4*)(xrow + k);
        float4 wa = *(const float4*)(wrow + k);
        As[lcol + 0][lrow] = xa.x; As[lcol + 1][lrow] = xa.y;
        As[lcol + 2][lrow] = xa.z; As[lcol + 3][lrow] = xa.w;
        Ws[lcol + 0][lrow] = wa.x; Ws[lcol + 1][lrow] = wa.y;
        Ws[lcol + 2][lrow] = wa.z; Ws[lcol + 3][lrow] = wa.w;
        __syncthreads();
        #pragma unroll
        for (int kk = 0; kk < 16; kk++) {
            float a[4], b[4];
            #pragma unroll
            for (int i = 0; i < 4; i++) a[i] = As[kk][ty * 4 + i];
            #pragma unroll
            for (int j = 0; j < 4; j++) b[j] = Ws[kk][tx * 4 + j];
            #pragma unroll
            for (int i = 0; i < 4; i++)
                #pragma unroll
                for (int j = 0; j < 4; j++)
                    acc[i][j] += a[i] * b[j];
        }
        __syncthreads();
    }

    float* Out = (which == 0) ? g_q : (which == 1) ? g_k : g_v;
    #pragma unroll
    for (int i = 0; i < 4; i++) {
        int m = m0 + ty * 4 + i;
        int b = m >> 11, s = m & (Sv - 1);
        #pragma unroll
        for (int j = 0; j < 4; j++) {
            int n = n0 + tx * 4 + j;
            int h = n >> 6, d = n & 63;
            Out[((size_t)(b * Hv + h) * Sv + s) * Dv + d] = acc[i][j] + bias[n];
        }
    }
}

// ---------------- scores: attn_raw[bh,m,n] = (Q[bh,m,:].K[bh,n,:]) * 0.125 + tb
__global__ __launch_bounds__(256)
void scores_kernel(float* __restrict__ attn) {
    __shared__ float As[16][65];
    __shared__ float Ws[16][65];
    const int t    = threadIdx.x;
    const int lrow = t >> 2;
    const int lcol = (t & 3) << 2;
    const int tx   = t & 15;
    const int ty   = t >> 4;
    const int bh   = blockIdx.z;
    const int m0   = blockIdx.y * 64;
    const int n0   = blockIdx.x * 64;

    const float* Q = g_q + (size_t)bh * Sv * Dv;
    const float* K = g_k + (size_t)bh * Sv * Dv;

    float acc[4][4] = {};
    for (int kt = 0; kt < 4; kt++) {      // D = 64 = 4*16
        int k = kt * 16 + lcol;
        float4 qa = *(const float4*)(Q + (size_t)(m0 + lrow) * Dv + k);
        float4 ka = *(const float4*)(K + (size_t)(n0 + lrow) * Dv + k);
        As[lcol + 0][lrow] = qa.x; As[lcol + 1][lrow] = qa.y;
        As[lcol + 2][lrow] = qa.z; As[lcol + 3][lrow] = qa.w;
        Ws[lcol + 0][lrow] = ka.x; Ws[lcol + 1][lrow] = ka.y;
        Ws[lcol + 2][lrow] = ka.z; Ws[lcol + 3][lrow] = ka.w;
        __syncthreads();
        #pragma unroll
        for (int kk = 0; kk < 16; kk++) {
            float a[4], b[4];
            #pragma unroll
            for (int i = 0; i < 4; i++) a[i] = As[kk][ty * 4 + i];
            #pragma unroll
            for (int j = 0; j < 4; j++) b[j] = Ws[kk][tx * 4 + j];
            #pragma unroll
            for (int i = 0; i < 4; i++)
                #pragma unroll
                for (int j = 0; j < 4; j++)
                    acc[i][j] += a[i] * b[j];
        }
        __syncthreads();
    }

    const float tbv = g_tb[bh];
    #pragma unroll
    for (int i = 0; i < 4; i++) {
        size_t rowbase = ((size_t)bh * Sv + (m0 + ty * 4 + i)) * Sv;
        #pragma unroll
        for (int j = 0; j < 4; j++) {
            int n = n0 + tx * 4 + j;
            attn[rowbase + n] = acc[i][j] * 0.125f + tbv;
        }
    }
}

// ---------------- row softmax over attn (in place), with mask -------------
__global__ __launch_bounds__(256)
void softmax_kernel(float* __restrict__ attn, const int* __restrict__ mask) {
    const size_t r = blockIdx.x;                 // 0 .. BH*S-1
    float* row = attn + r * (size_t)Sv;
    const int b = (int)(r / (size_t)(Hv * Sv));
    const int* mrow = mask + b * Sv;
    const int t = threadIdx.x;

    float v[8];
    float mx = -INFINITY;
    #pragma unroll
    for (int i = 0; i < 8; i++) {
        int c = t + i * 256;
        float f = row[c];
        if (mrow[c] == 0) f = -INFINITY;
        v[i] = f;
        mx = fmaxf(mx, f);
    }
    __shared__ float red[8];
    #pragma unroll
    for (int o = 16; o > 0; o >>= 1) mx = fmaxf(mx, __shfl_xor_sync(0xffffffffu, mx, o));
    if ((t & 31) == 0) red[t >> 5] = mx;
    __syncthreads();
    float bm = red[0];
    #pragma unroll
    for (int w = 1; w < 8; w++) bm = fmaxf(bm, red[w]);
    __syncthreads();

    float sum = 0.f;
    #pragma unroll
    for (int i = 0; i < 8; i++) {
        float e = __expf(v[i] - bm);
        v[i] = e;
        sum += e;
    }
    #pragma unroll
    for (int o = 16; o > 0; o >>= 1) sum += __shfl_xor_sync(0xffffffffu, sum, o);
    if ((t & 31) == 0) red[t >> 5] = sum;
    __syncthreads();
    float tot = 0.f;
    #pragma unroll
    for (int w = 0; w < 8; w++) tot += red[w];
    float inv = 1.f / tot;
    #pragma unroll
    for (int i = 0; i < 8; i++) row[t + i * 256] = v[i] * inv;
}

// ---------------- ctx = attn @ V : [2048x2048] @ [2048x64] per (b,h) ------
__global__ __launch_bounds__(256)
void av_kernel(const float* __restrict__ attn) {
    __shared__ float As[16][65];
    __shared__ float Vs[16][65];
    const int t    = threadIdx.x;
    const int lrow = t >> 2;
    const int lcol = (t & 3) << 2;
    const int tx   = t & 15;
    const int ty   = t >> 4;
    const int vk   = t >> 4;           // 0..15
    const int vn   = (t & 15) << 2;    // 0..60
    const int bh   = blockIdx.z;
    const int m0   = blockIdx.y * 64;

    const float* A = attn + (size_t)bh * Sv * Sv;
    const float* V = g_v  + (size_t)bh * Sv * Dv;

    float acc[4][4] = {};
    for (int kt = 0; kt < Sv / 16; kt++) {
        float4 aa = *(const float4*)(A + (size_t)(m0 + lrow) * Sv + kt * 16 + lcol);
        As[lcol + 0][lrow] = aa.x; As[lcol + 1][lrow] = aa.y;
        As[lcol + 2][lrow] = aa.z; As[lcol + 3][lrow] = aa.w;
        float4 va = *(const float4*)(V + (size_t)(kt * 16 + vk) * Dv + vn);
        Vs[vk][vn + 0] = va.x; Vs[vk][vn + 1] = va.y;
        Vs[vk][vn + 2] = va.z; Vs[vk][vn + 3] = va.w;
        __syncthreads();
        #pragma unroll
        for (int kk = 0; kk < 16; kk++) {
            float a[4], b[4];
            #pragma unroll
            for (int i = 0; i < 4; i++) a[i] = As[kk][ty * 4 + i];
            #pragma unroll
            for (int j = 0; j < 4; j++) b[j] = Vs[kk][tx * 4 + j];
            #pragma unroll
            for (int i = 0; i < 4; i++)
                #pragma unroll
                for (int j = 0; j < 4; j++)
                    acc[i][j] += a[i] * b[j];
        }
        __syncthreads();
    }

    #pragma unroll
    for (int i = 0; i < 4; i++) {
        size_t rowbase = ((size_t)bh * Sv + (m0 + ty * 4 + i)) * Dv;
        #pragma unroll
        for (int j = 0; j < 4; j++)
            g_ctx[rowbase + tx * 4 + j] = acc[i][j];
    }
}

// ---------------- out = ctx(reassembled) @ Wo^T + bo ----------------------
__global__ __launch_bounds__(256)
void oproj_kernel(const float* __restrict__ Wo, const float* __restrict__ bo,
                  float* __restrict__ out) {
    __shared__ float As[16][65];
    __shared__ float Ws[16][65];
    const int t    = threadIdx.x;
    const int lrow = t >> 2;
    const int lcol = (t & 3) << 2;
    const int tx   = t & 15;
    const int ty   = t >> 4;
    const int m0   = blockIdx.y * 64;
    const int n0   = blockIdx.x * 64;

    const int m = m0 + lrow;
    const int b = m >> 11, s = m & (Sv - 1);
    const float* wrow = Wo + (size_t)(n0 + lrow) * Ev;

    float acc[4][4] = {};
    for (int kt = 0; kt < Ev / 16; kt++) {
        int k = kt * 16 + lcol;
        int h = k >> 6, d = k & 63;
        float4 xa = *(const float4*)(g_ctx + ((size_t)(b * Hv + h) * Sv + s) * Dv + d);
        float4 wa = *(const float4*)(wrow + k);
        As[lcol + 0][lrow] = xa.x; As[lcol + 1][lrow] = xa.y;
        As[lcol + 2][lrow] = xa.z; As[lcol + 3][lrow] = xa.w;
        Ws[lcol + 0][lrow] = wa.x; Ws[lcol + 1][lrow] = wa.y;
        Ws[lcol + 2][lrow] = wa.z; Ws[lcol + 3][lrow] = wa.w;
        __syncthreads();
        #pragma unroll
        for (int kk = 0; kk < 16; kk++) {
            float a[4], bb[4];
            #pragma unroll
            for (int i = 0; i < 4; i++) a[i] = As[kk][ty * 4 + i];
            #pragma unroll
            for (int j = 0; j < 4; j++) bb[j] = Ws[kk][tx * 4 + j];
            #pragma unroll
            for (int i = 0; i < 4; i++)
                #pragma unroll
                for (int j = 0; j < 4; j++)
                    acc[i][j] += a[i] * bb[j];
        }
        __syncthreads();
    }

    #pragma unroll
    for (int i = 0; i < 4; i++) {
        size_t rowbase = (size_t)(m0 + ty * 4 + i) * Ev;
        #pragma unroll
        for (int j = 0; j < 4; j++) {
            int n = n0 + tx * 4 + j;
            out[rowbase + n] = acc[i][j] + bo[n];
        }
    }
}

// ---------------- launch ---------------------------------------------------
extern "C" void kernel_launch(void* const* d_in, const int* in_sizes, int n_in,
                              void* d_out, int out_size) {
    const float* query     = (const float*)d_in[0];
    const float* key       = (const float*)d_in[1];
    const float* value     = (const float*)d_in[2];
    const float* task_bias = (const float*)d_in[3];
    const int*   mask      = (const int*)  d_in[4];
    const float* Wq  = (const float*)d_in[5];  const float* bq  = (const float*)d_in[6];
    const float* Wk  = (const float*)d_in[7];  const float* bk  = (const float*)d_in[8];
    const float* Wv  = (const float*)d_in[9];  const float* bv  = (const float*)d_in[10];
    const float* Wtb = (const float*)d_in[11]; const float* btb = (const float*)d_in[12];
    const float* Wo  = (const float*)d_in[13]; const float* bo  = (const float*)d_in[14];

    float* outp = (float*)d_out;
    float* attn = outp + (size_t)Bv * Sv * Ev;   // second output region

    // 1. task bias projection
    tb_kernel<<<1, 32>>>(task_bias, Wtb, btb);

    // 2. Q/K/V projections into head layout
    dim3 pg(Ev / 64, Mv / 64);                   // (12, 64)
    proj_kernel<<<pg, 256>>>(query, Wq, bq, 0);
    proj_kernel<<<pg, 256>>>(key,   Wk, bk, 1);
    proj_kernel<<<pg, 256>>>(value, Wv, bv, 2);

    // 3. raw scores (scaled + tb) directly into attn output region
    dim3 sg(Sv / 64, Sv / 64, BHv);              // (32, 32, 24)
    scores_kernel<<<sg, 256>>>(attn);

    // 4. softmax in place (one block per row)
    softmax_kernel<<<BHv * Sv, 256>>>(attn, mask);

    // 5. ctx = attn @ V
    dim3 ag(1, Sv / 64, BHv);                    // (1, 32, 24)
    av_kernel<<<ag, 256>>>(attn);

    // 6. output projection
    oproj_kernel<<<pg, 256>>>(Wo, bo, outp);
}

// round 14
// speedup vs baseline: 1.0001x; 1.0001x over previous
#include <cuda_runtime.h>
#include <cuda_bf16.h>
#include <math.h>

// ---------------- problem constants ----------------
#define Bv   2
#define Sv   2048
#define Ev   768
#define Hv   12
#define Dv   64
#define TBv  128
#define Mv   (Bv*Sv)      // 4096
#define BHv  (Bv*Hv)      // 24

// ---------------- scratch (device globals; no allocation at runtime) ------
__device__ float g_q  [BHv * Sv * Dv];   // [b,h,s,d]
__device__ float g_k  [BHv * Sv * Dv];
__device__ float g_v  [BHv * Sv * Dv];
__device__ float g_ctx[BHv * Sv * Dv];
__device__ float g_tb [BHv];

// ---------------- task-bias projection: tb[b,h] = task_bias[b,:] . Wtb[h,:] + btb[h]
__global__ void tb_kernel(const float* __restrict__ task_bias,
                          const float* __restrict__ Wtb,
                          const float* __restrict__ btb) {
    int i = threadIdx.x;
    if (i < BHv) {
        int b = i / Hv, h = i % Hv;
        float s = btb[h];
        const float* tbp = task_bias + b * TBv;
        const float* wp  = Wtb + h * TBv;
        #pragma unroll 8
        for (int t = 0; t < TBv; t++) s += tbp[t] * wp[t];
        g_tb[i] = s;
    }
}

// ---------------- QKV projection GEMM -------------------------------------
// C = X @ W^T + bias ; X [4096,768], W [768,768] row-major (W[n][k]).
// Output scattered into head layout g_{q,k,v}[((b*H+h)*S+s)*D + d].
__global__ __launch_bounds__(256)
void proj_kernel(const float* __restrict__ X, const float* __restrict__ W,
                 const float* __restrict__ bias, int which) {
    __shared__ float As[16][65];
    __shared__ float Ws[16][65];
    const int t    = threadIdx.x;
    const int lrow = t >> 2;            // 0..63
    const int lcol = (t & 3) << 2;      // 0,4,8,12
    const int tx   = t & 15;
    const int ty   = t >> 4;
    const int m0   = blockIdx.y * 64;
    const int n0   = blockIdx.x * 64;

    const float* xrow = X + (size_t)(m0 + lrow) * Ev;
    const float* wrow = W + (size_t)(n0 + lrow) * Ev;

    float acc[4][4] = {};
    for (int kt = 0; kt < Ev / 16; kt++) {
        int k = kt * 16 + lcol;
        float4 xa = *(const float4*)(xrow + k);
        float4 wa = *(const float4*)(wrow + k);
        As[lcol + 0][lrow] = xa.x; As[lcol + 1][lrow] = xa.y;
        As[lcol + 2][lrow] = xa.z; As[lcol + 3][lrow] = xa.w;
        Ws[lcol + 0][lrow] = wa.x; Ws[lcol + 1][lrow] = wa.y;
        Ws[lcol + 2][lrow] = wa.z; Ws[lcol + 3][lrow] = wa.w;
        __syncthreads();
        #pragma unroll
        for (int kk = 0; kk < 16; kk++) {
            float a[4], b[4];
            #pragma unroll
            for (int i = 0; i < 4; i++) a[i] = As[kk][ty * 4 + i];
            #pragma unroll
            for (int j = 0; j < 4; j++) b[j] = Ws[kk][tx * 4 + j];
            #pragma unroll
            for (int i = 0; i < 4; i++)
                #pragma unroll
                for (int j = 0; j < 4; j++)
                    acc[i][j] += a[i] * b[j];
        }
        __syncthreads();
    }

    float* Out = (which == 0) ? g_q : (which == 1) ? g_k : g_v;
    #pragma unroll
    for (int i = 0; i < 4; i++) {
        int m = m0 + ty * 4 + i;
        int b = m >> 11, s = m & (Sv - 1);
        #pragma unroll
        for (int j = 0; j < 4; j++) {
            int n = n0 + tx * 4 + j;
            int h = n >> 6, d = n & 63;
            Out[((size_t)(b * Hv + h) * Sv + s) * Dv + d] = acc[i][j] + bias[n];
        }
    }
}

// ---------------- scores: attn_raw[bh,m,n] = (Q[bh,m,:].K[bh,n,:]) * 0.125 + tb
__global__ __launch_bounds__(256)
void scores_kernel(float* __restrict__ attn) {
    __shared__ float As[16][65];
    __shared__ float Ws[16][65];
    const int t    = threadIdx.x;
    const int lrow = t >> 2;
    const int lcol = (t & 3) << 2;
    const int tx   = t & 15;
    const int ty   = t >> 4;
    const int bh   = blockIdx.z;
    const int m0   = blockIdx.y * 64;
    const int n0   = blockIdx.x * 64;

    const float* Q = g_q + (size_t)bh * Sv * Dv;
    const float* K = g_k + (size_t)bh * Sv * Dv;

    float acc[4][4] = {};
    for (int kt = 0; kt < 4; kt++) {      // D = 64 = 4*16
        int k = kt * 16 + lcol;
        float4 qa = *(const float4*)(Q + (size_t)(m0 + lrow) * Dv + k);
        float4 ka = *(const float4*)(K + (size_t)(n0 + lrow) * Dv + k);
        As[lcol + 0][lrow] = qa.x; As[lcol + 1][lrow] = qa.y;
        As[lcol + 2][lrow] = qa.z; As[lcol + 3][lrow] = qa.w;
        Ws[lcol + 0][lrow] = ka.x; Ws[lcol + 1][lrow] = ka.y;
        Ws[lcol + 2][lrow] = ka.z; Ws[lcol + 3][lrow] = ka.w;
        __syncthreads();
        #pragma unroll
        for (int kk = 0; kk < 16; kk++) {
            float a[4], b[4];
            #pragma unroll
            for (int i = 0; i < 4; i++) a[i] = As[kk][ty * 4 + i];
            #pragma unroll
            for (int j = 0; j < 4; j++) b[j] = Ws[kk][tx * 4 + j];
            #pragma unroll
            for (int i = 0; i < 4; i++)
                #pragma unroll
                for (int j = 0; j < 4; j++)
                    acc[i][j] += a[i] * b[j];
        }
        __syncthreads();
    }

    const float tbv = g_tb[bh];
    #pragma unroll
    for (int i = 0; i < 4; i++) {
        size_t rowbase = ((size_t)bh * Sv + (m0 + ty * 4 + i)) * Sv;
        #pragma unroll
        for (int j = 0; j < 4; j++) {
            int n = n0 + tx * 4 + j;
            attn[rowbase + n] = acc[i][j] * 0.125f + tbv;
        }
    }
}

// ---------------- row softmax over attn (in place), with mask -------------
__global__ __launch_bounds__(256)
void softmax_kernel(float* __restrict__ attn, const int* __restrict__ mask) {
    const size_t r = blockIdx.x;                 // 0 .. BH*S-1
    float* row = attn + r * (size_t)Sv;
    const int b = (int)(r / (size_t)(Hv * Sv));
    const int* mrow = mask + b * Sv;
    const int t = threadIdx.x;

    float v[8];
    float mx = -INFINITY;
    #pragma unroll
    for (int i = 0; i < 8; i++) {
        int c = t + i * 256;
        float f = row[c];
        if (mrow[c] == 0) f = -INFINITY;
        v[i] = f;
        mx = fmaxf(mx, f);
    }
    __shared__ float red[8];
    #pragma unroll
    for (int o = 16; o > 0; o >>= 1) mx = fmaxf(mx, __shfl_xor_sync(0xffffffffu, mx, o));
    if ((t & 31) == 0) red[t >> 5] = mx;
    __syncthreads();
    float bm = red[0];
    #pragma unroll
    for (int w = 1; w < 8; w++) bm = fmaxf(bm, red[w]);
    __syncthreads();

    float sum = 0.f;
    #pragma unroll
    for (int i = 0; i < 8; i++) {
        float e = __expf(v[i] - bm);
        v[i] = e;
        sum += e;
    }
    #pragma unroll
    for (int o = 16; o > 0; o >>= 1) sum += __shfl_xor_sync(0xffffffffu, sum, o);
    if ((t & 31) == 0) red[t >> 5] = sum;
    __syncthreads();
    float tot = 0.f;
    #pragma unroll
    for (int w = 0; w < 8; w++) tot += red[w];
    float inv = 1.f / tot;
    #pragma unroll
    for (int i = 0; i < 8; i++) row[t + i * 256] = v[i] * inv;
}

// ---------------- ctx = attn @ V : [2048x2048] @ [2048x64] per (b,h) ------
__global__ __launch_bounds__(256)
void av_kernel(const float* __restrict__ attn) {
    __shared__ float As[16][65];
    __shared__ float Vs[16][65];
    const int t    = threadIdx.x;
    const int lrow = t >> 2;
    const int lcol = (t & 3) << 2;
    const int tx   = t & 15;
    const int ty   = t >> 4;
    const int vk   = t >> 4;           // 0..15
    const int vn   = (t & 15) << 2;    // 0..60
    const int bh   = blockIdx.z;
    const int m0   = blockIdx.y * 64;

    const float* A = attn + (size_t)bh * Sv * Sv;
    const float* V = g_v  + (size_t)bh * Sv * Dv;

    float acc[4][4] = {};
    for (int kt = 0; kt < Sv / 16; kt++) {
        float4 aa = *(const float4*)(A + (size_t)(m0 + lrow) * Sv + kt * 16 + lcol);
        As[lcol + 0][lrow] = aa.x; As[lcol + 1][lrow] = aa.y;
        As[lcol + 2][lrow] = aa.z; As[lcol + 3][lrow] = aa.w;
        float4 va = *(const float4*)(V + (size_t)(kt * 16 + vk) * Dv + vn);
        Vs[vk][vn + 0] = va.x; Vs[vk][vn + 1] = va.y;
        Vs[vk][vn + 2] = va.z; Vs[vk][vn + 3] = va.w;
        __syncthreads();
        #pragma unroll
        for (int kk = 0; kk < 16; kk++) {
            float a[4], b[4];
            #pragma unroll
            for (int i = 0; i < 4; i++) a[i] = As[kk][ty * 4 + i];
            #pragma unroll
            for (int j = 0; j < 4; j++) b[j] = Vs[kk][tx * 4 + j];
            #pragma unroll
            for (int i = 0; i < 4; i++)
                #pragma unroll
                for (int j = 0; j < 4; j++)
                    acc[i][j] += a[i] * b[j];
        }
        __syncthreads();
    }

    #pragma unroll
    for (int i = 0; i < 4; i++) {
        size_t rowbase = ((size_t)bh * Sv + (m0 + ty * 4 + i)) * Dv;
        #pragma unroll
        for (int j = 0; j < 4; j++)
            g_ctx[rowbase + tx * 4 + j] = acc[i][j];
    }
}

// ---------------- out = ctx(reassembled) @ Wo^T + bo ----------------------
__global__ __launch_bounds__(256)
void oproj_kernel(const float* __restrict__ Wo, const float* __restrict__ bo,
                  float* __restrict__ out) {
    __shared__ float As[16][65];
    __shared__ float Ws[16][65];
    const int t    = threadIdx.x;
    const int lrow = t >> 2;
    const int lcol = (t & 3) << 2;
    const int tx   = t & 15;
    const int ty   = t >> 4;
    const int m0   = blockIdx.y * 64;
    const int n0   = blockIdx.x * 64;

    const int m = m0 + lrow;
    const int b = m >> 11, s = m & (Sv - 1);
    const float* wrow = Wo + (size_t)(n0 + lrow) * Ev;

    float acc[4][4] = {};
    for (int kt = 0; kt < Ev / 16; kt++) {
        int k = kt * 16 + lcol;
        int h = k >> 6, d = k & 63;
        float4 xa = *(const float4*)(g_ctx + ((size_t)(b * Hv + h) * Sv + s) * Dv + d);
        float4 wa = *(const float4*)(wrow + k);
        As[lcol + 0][lrow] = xa.x; As[lcol + 1][lrow] = xa.y;
        As[lcol + 2][lrow] = xa.z; As[lcol + 3][lrow] = xa.w;
        Ws[lcol + 0][lrow] = wa.x; Ws[lcol + 1][lrow] = wa.y;
        Ws[lcol + 2][lrow] = wa.z; Ws[lcol + 3][lrow] = wa.w;
        __syncthreads();
        #pragma unroll
        for (int kk = 0; kk < 16; kk++) {
            float a[4], bb[4];
            #pragma unroll
            for (int i = 0; i < 4; i++) a[i] = As[kk][ty * 4 + i];
            #pragma unroll
            for (int j = 0; j < 4; j++) bb[j] = Ws[kk][tx * 4 + j];
            #pragma unroll
            for (int i = 0; i < 4; i++)
                #pragma unroll
                for (int j = 0; j < 4; j++)
                    acc[i][j] += a[i] * bb[j];
        }
        __syncthreads();
    }

    #pragma unroll
    for (int i = 0; i < 4; i++) {
        size_t rowbase = (size_t)(m0 + ty * 4 + i) * Ev;
        #pragma unroll
        for (int j = 0; j < 4; j++) {
            int n = n0 + tx * 4 + j;
            out[rowbase + n] = acc[i][j] + bo[n];
        }
    }
}

// ---------------- launch ---------------------------------------------------
extern "C" void kernel_launch(void* const* d_in, const int* in_sizes, int n_in,
                              void* d_out, int out_size) {
    const float* query     = (const float*)d_in[0];
    const float* key       = (const float*)d_in[1];
    const float* value     = (const float*)d_in[2];
    const float* task_bias = (const float*)d_in[3];
    const int*   mask      = (const int*)  d_in[4];
    const float* Wq  = (const float*)d_in[5];  const float* bq  = (const float*)d_in[6];
    const float* Wk  = (const float*)d_in[7];  const float* bk  = (const float*)d_in[8];
    const float* Wv  = (const float*)d_in[9];  const float* bv  = (const float*)d_in[10];
    const float* Wtb = (const float*)d_in[11]; const float* btb = (const float*)d_in[12];
    const float* Wo  = (const float*)d_in[13]; const float* bo  = (const float*)d_in[14];

    float* outp = (float*)d_out;
    float* attn = outp + (size_t)Bv * Sv * Ev;   // second output region

    // 1. task bias projection
    tb_kernel<<<1, 32>>>(task_bias, Wtb, btb);

    // 2. Q/K/V projections into head layout
    dim3 pg(Ev / 64, Mv / 64);                   // (12, 64)
    proj_kernel<<<pg, 256>>>(query, Wq, bq, 0);
    proj_kernel<<<pg, 256>>>(key,   Wk, bk, 1);
    proj_kernel<<<pg, 256>>>(value, Wv, bv, 2);

    // 3. raw scores (scaled + tb) directly into attn output region
    dim3 sg(Sv / 64, Sv / 64, BHv);              // (32, 32, 24)
    scores_kernel<<<sg, 256>>>(attn);

    // 4. softmax in place (one block per row)
    softmax_kernel<<<BHv * Sv, 256>>>(attn, mask);

    // 5. ctx = attn @ V
    dim3 ag(1, Sv / 64, BHv);                    // (1, 32, 24)
    av_kernel<<<ag, 256>>>(attn);

    // 6. output projection
    oproj_kernel<<<pg, 256>>>(Wo, bo, outp);
}

// round 15
// speedup vs baseline: 2.3394x; 2.3391x over previous
#include <cuda_runtime.h>
#include <math.h>

// ---------------- problem constants ----------------
#define Bv   2
#define Sv   2048
#define Ev   768
#define Hv   12
#define Dv   64
#define TBv  128
#define Mv   (Bv*Sv)      // 4096
#define BHv  (Bv*Hv)      // 24
#define SA   20           // smem row stride (floats) -> conflict-free frag loads

// ---------------- scratch (device globals) ------
__device__ float g_q  [BHv * Sv * Dv];   // [bh][s][d], tf32-rounded
__device__ float g_k  [BHv * Sv * Dv];   // [bh][s][d], tf32-rounded
__device__ float g_vt [BHv * Dv * Sv];   // [bh][d][s], TRANSPOSED, tf32-rounded
__device__ float g_ctx[BHv * Sv * Dv];   // [bh][s][d], tf32-rounded
__device__ float g_tb [BHv];

// ---------------- helpers --------------------------------------------------
__device__ __forceinline__ unsigned f2tf(float f) {
    unsigned u;
    asm("cvt.rna.tf32.f32 %0, %1;" : "=r"(u) : "f"(f));
    return u;
}

__device__ __forceinline__ void mma8(float c[4], const unsigned a[4], const unsigned b[2]) {
    asm volatile(
        "mma.sync.aligned.m16n8k8.row.col.f32.tf32.tf32.f32 "
        "{%0,%1,%2,%3},{%4,%5,%6,%7},{%8,%9},{%0,%1,%2,%3};"
        : "+f"(c[0]), "+f"(c[1]), "+f"(c[2]), "+f"(c[3])
        : "r"(a[0]), "r"(a[1]), "r"(a[2]), "r"(a[3]), "r"(b[0]), "r"(b[1]));
}

// ---------------- task-bias projection -------------------------------------
__global__ void tb_kernel(const float* __restrict__ task_bias,
                          const float* __restrict__ Wtb,
                          const float* __restrict__ btb) {
    int i = threadIdx.x;
    if (i < BHv) {
        int b = i / Hv, h = i % Hv;
        float s = btb[h];
        const float* tbp = task_bias + b * TBv;
        const float* wp  = Wtb + h * TBv;
        #pragma unroll 8
        for (int t = 0; t < TBv; t++) s += tbp[t] * wp[t];
        g_tb[i] = s;
    }
}

// ---------------- QKV projection: C = X @ W^T + bias (tf32 MMA) ------------
// 128x128 block, 8 warps (4x2), warp tile 32x64. Outputs tf32-rounded into
// head layout (q,k: [bh][s][d]; v: transposed [bh][d][s]).
__global__ __launch_bounds__(256)
void proj_tf32(const float* __restrict__ X, const float* __restrict__ W,
               const float* __restrict__ bias, int which) {
    __shared__ unsigned As[128 * SA];
    __shared__ unsigned Bs[128 * SA];
    const int t    = threadIdx.x;
    const int m0   = blockIdx.y * 128;
    const int n0   = blockIdx.x * 128;
    const int w    = t >> 5, lane = t & 31;
    const int g    = lane >> 2, tig = lane & 3;
    const int wm   = (w & 3) * 32, wn = (w >> 2) * 64;
    const int srow = t >> 2, scg = (t & 3) << 2;

    float acc[2][8][4] = {};

    for (int kt = 0; kt < Ev / 16; kt++) {
        const int k0 = kt * 16;
        #pragma unroll
        for (int r = 0; r < 2; r++) {
            int row = srow + r * 64;
            float4 xa = *(const float4*)(X + (size_t)(m0 + row) * Ev + k0 + scg);
            As[row * SA + scg + 0] = f2tf(xa.x); As[row * SA + scg + 1] = f2tf(xa.y);
            As[row * SA + scg + 2] = f2tf(xa.z); As[row * SA + scg + 3] = f2tf(xa.w);
            float4 wa = *(const float4*)(W + (size_t)(n0 + row) * Ev + k0 + scg);
            Bs[row * SA + scg + 0] = f2tf(wa.x); Bs[row * SA + scg + 1] = f2tf(wa.y);
            Bs[row * SA + scg + 2] = f2tf(wa.z); Bs[row * SA + scg + 3] = f2tf(wa.w);
        }
        __syncthreads();
        #pragma unroll
        for (int ks = 0; ks < 2; ks++) {
            const int kk = ks * 8;
            unsigned a[2][4], b[8][2];
            #pragma unroll
            for (int mt = 0; mt < 2; mt++) {
                int r = wm + mt * 16 + g;
                a[mt][0] = As[r * SA + kk + tig];
                a[mt][1] = As[(r + 8) * SA + kk + tig];
                a[mt][2] = As[r * SA + kk + tig + 4];
                a[mt][3] = As[(r + 8) * SA + kk + tig + 4];
            }
            #pragma unroll
            for (int nt = 0; nt < 8; nt++) {
                int c = wn + nt * 8 + g;
                b[nt][0] = Bs[c * SA + kk + tig];
                b[nt][1] = Bs[c * SA + kk + tig + 4];
            }
            #pragma unroll
            for (int mt = 0; mt < 2; mt++)
                #pragma unroll
                for (int nt = 0; nt < 8; nt++)
                    mma8(acc[mt][nt], a[mt], b[nt]);
        }
        __syncthreads();
    }

    float* Out = (which == 0) ? g_q : g_k;
    #pragma unroll
    for (int mt = 0; mt < 2; mt++)
        #pragma unroll
        for (int half = 0; half < 2; half++) {
            int m = m0 + wm + mt * 16 + g + half * 8;
            int b = m >> 11, s = m & (Sv - 1);
            #pragma unroll
            for (int nt = 0; nt < 8; nt++) {
                int col = n0 + wn + nt * 8 + 2 * tig;
                float v0 = acc[mt][nt][half * 2 + 0] + bias[col];
                float v1 = acc[mt][nt][half * 2 + 1] + bias[col + 1];
                int h = col >> 6, d = col & 63;
                if (which == 2) {
                    size_t base = ((size_t)(b * Hv + h) * Dv + d) * Sv + s;
                    g_vt[base]      = __uint_as_float(f2tf(v0));
                    g_vt[base + Sv] = __uint_as_float(f2tf(v1));
                } else {
                    *(float2*)&Out[((size_t)(b * Hv + h) * Sv + s) * Dv + d] =
                        make_float2(__uint_as_float(f2tf(v0)), __uint_as_float(f2tf(v1)));
                }
            }
        }
}

// ---------------- scores: attn = (Q K^T)*0.125 + tb (tf32 MMA) -------------
__global__ __launch_bounds__(256)
void scores_tf32(float* __restrict__ attn) {
    __shared__ unsigned As[128 * SA];
    __shared__ unsigned Bs[128 * SA];
    const int t    = threadIdx.x;
    const int bh   = blockIdx.z;
    const int m0   = blockIdx.y * 128;
    const int n0   = blockIdx.x * 128;
    const int w    = t >> 5, lane = t & 31;
    const int g    = lane >> 2, tig = lane & 3;
    const int wm   = (w & 3) * 32, wn = (w >> 2) * 64;
    const int srow = t >> 2, scg = (t & 3) << 2;

    const float* Q = g_q + (size_t)bh * Sv * Dv;
    const float* K = g_k + (size_t)bh * Sv * Dv;

    float acc[2][8][4] = {};

    for (int kt = 0; kt < Dv / 16; kt++) {
        const int k0 = kt * 16;
        #pragma unroll
        for (int r = 0; r < 2; r++) {
            int row = srow + r * 64;
            float4 qa = *(const float4*)(Q + (size_t)(m0 + row) * Dv + k0 + scg);
            As[row * SA + scg + 0] = __float_as_uint(qa.x);
            As[row * SA + scg + 1] = __float_as_uint(qa.y);
            As[row * SA + scg + 2] = __float_as_uint(qa.z);
            As[row * SA + scg + 3] = __float_as_uint(qa.w);
            float4 ka = *(const float4*)(K + (size_t)(n0 + row) * Dv + k0 + scg);
            Bs[row * SA + scg + 0] = __float_as_uint(ka.x);
            Bs[row * SA + scg + 1] = __float_as_uint(ka.y);
            Bs[row * SA + scg + 2] = __float_as_uint(ka.z);
            Bs[row * SA + scg + 3] = __float_as_uint(ka.w);
        }
        __syncthreads();
        #pragma unroll
        for (int ks = 0; ks < 2; ks++) {
            const int kk = ks * 8;
            unsigned a[2][4], b[8][2];
            #pragma unroll
            for (int mt = 0; mt < 2; mt++) {
                int r = wm + mt * 16 + g;
                a[mt][0] = As[r * SA + kk + tig];
                a[mt][1] = As[(r + 8) * SA + kk + tig];
                a[mt][2] = As[r * SA + kk + tig + 4];
                a[mt][3] = As[(r + 8) * SA + kk + tig + 4];
            }
            #pragma unroll
            for (int nt = 0; nt < 8; nt++) {
                int c = wn + nt * 8 + g;
                b[nt][0] = Bs[c * SA + kk + tig];
                b[nt][1] = Bs[c * SA + kk + tig + 4];
            }
            #pragma unroll
            for (int mt = 0; mt < 2; mt++)
                #pragma unroll
                for (int nt = 0; nt < 8; nt++)
                    mma8(acc[mt][nt], a[mt], b[nt]);
        }
        __syncthreads();
    }

    const float tbv = g_tb[bh];
    #pragma unroll
    for (int mt = 0; mt < 2; mt++)
        #pragma unroll
        for (int half = 0; half < 2; half++) {
            int m = m0 + wm + mt * 16 + g + half * 8;
            size_t rowbase = ((size_t)bh * Sv + m) * Sv;
            #pragma unroll
            for (int nt = 0; nt < 8; nt++) {
                int col = n0 + wn + nt * 8 + 2 * tig;
                float v0 = acc[mt][nt][half * 2 + 0] * 0.125f + tbv;
                float v1 = acc[mt][nt][half * 2 + 1] * 0.125f + tbv;
                *(float2*)&attn[rowbase + col] = make_float2(v0, v1);
            }
        }
}

// ---------------- row softmax (in place), with mask -------------------------
__global__ __launch_bounds__(256)
void softmax_kernel(float* __restrict__ attn, const int* __restrict__ mask) {
    const size_t r = blockIdx.x;
    float* row = attn + r * (size_t)Sv;
    const int b = (int)(r / (size_t)(Hv * Sv));
    const int* mrow = mask + b * Sv;
    const int t = threadIdx.x;

    float v[8];
    float mx = -INFINITY;
    #pragma unroll
    for (int i = 0; i < 8; i++) {
        int c = t + i * 256;
        float f = row[c];
        if (mrow[c] == 0) f = -INFINITY;
        v[i] = f;
        mx = fmaxf(mx, f);
    }
    __shared__ float red[8];
    #pragma unroll
    for (int o = 16; o > 0; o >>= 1) mx = fmaxf(mx, __shfl_xor_sync(0xffffffffu, mx, o));
    if ((t & 31) == 0) red[t >> 5] = mx;
    __syncthreads();
    float bm = red[0];
    #pragma unroll
    for (int wq = 1; wq < 8; wq++) bm = fmaxf(bm, red[wq]);
    __syncthreads();

    float sum = 0.f;
    #pragma unroll
    for (int i = 0; i < 8; i++) {
        float e = __expf(v[i] - bm);
        v[i] = e;
        sum += e;
    }
    #pragma unroll
    for (int o = 16; o > 0; o >>= 1) sum += __shfl_xor_sync(0xffffffffu, sum, o);
    if ((t & 31) == 0) red[t >> 5] = sum;
    __syncthreads();
    float tot = 0.f;
    #pragma unroll
    for (int wq = 0; wq < 8; wq++) tot += red[wq];
    float inv = 1.f / tot;
    #pragma unroll
    for (int i = 0; i < 8; i++) row[t + i * 256] = v[i] * inv;
}

// ---------------- ctx = attn @ V (tf32 MMA, V pre-transposed) ---------------
// 128x64 block, 8 warps (4x2), warp tile 32x32.
__global__ __launch_bounds__(256)
void av_tf32(const float* __restrict__ attn) {
    __shared__ unsigned As[128 * SA];
    __shared__ unsigned Bs[64 * SA];
    const int t    = threadIdx.x;
    const int bh   = blockIdx.z;
    const int m0   = blockIdx.y * 128;
    const int w    = t >> 5, lane = t & 31;
    const int g    = lane >> 2, tig = lane & 3;
    const int wm   = (w & 3) * 32, wn = (w >> 2) * 32;
    const int srow = t >> 2, scg = (t & 3) << 2;

    const float* A  = attn + (size_t)bh * Sv * Sv;
    const float* VT = g_vt + (size_t)bh * Dv * Sv;

    float acc[2][4][4] = {};

    for (int kt = 0; kt < Sv / 16; kt++) {
        const int k0 = kt * 16;
        #pragma unroll
        for (int r = 0; r < 2; r++) {
            int row = srow + r * 64;
            float4 aa = *(const float4*)(A + (size_t)(m0 + row) * Sv + k0 + scg);
            As[row * SA + scg + 0] = f2tf(aa.x); As[row * SA + scg + 1] = f2tf(aa.y);
            As[row * SA + scg + 2] = f2tf(aa.z); As[row * SA + scg + 3] = f2tf(aa.w);
        }
        {   // V^T tile: 64 rows (d) x 16 cols (s), k-contiguous, pre-rounded bits
            float4 va = *(const float4*)(VT + (size_t)srow * Sv + k0 + scg);
            Bs[srow * SA + scg + 0] = __float_as_uint(va.x);
            Bs[srow * SA + scg + 1] = __float_as_uint(va.y);
            Bs[srow * SA + scg + 2] = __float_as_uint(va.z);
            Bs[srow * SA + scg + 3] = __float_as_uint(va.w);
        }
        __syncthreads();
        #pragma unroll
        for (int ks = 0; ks < 2; ks++) {
            const int kk = ks * 8;
            unsigned a[2][4], b[4][2];
            #pragma unroll
            for (int mt = 0; mt < 2; mt++) {
                int r = wm + mt * 16 + g;
                a[mt][0] = As[r * SA + kk + tig];
                a[mt][1] = As[(r + 8) * SA + kk + tig];
                a[mt][2] = As[r * SA + kk + tig + 4];
                a[mt][3] = As[(r + 8) * SA + kk + tig + 4];
            }
            #pragma unroll
            for (int nt = 0; nt < 4; nt++) {
                int c = wn + nt * 8 + g;
                b[nt][0] = Bs[c * SA + kk + tig];
                b[nt][1] = Bs[c * SA + kk + tig + 4];
            }
            #pragma unroll
            for (int mt = 0; mt < 2; mt++)
                #pragma unroll
                for (int nt = 0; nt < 4; nt++)
                    mma8(acc[mt][nt], a[mt], b[nt]);
        }
        __syncthreads();
    }

    #pragma unroll
    for (int mt = 0; mt < 2; mt++)
        #pragma unroll
        for (int half = 0; half < 2; half++) {
            int m = m0 + wm + mt * 16 + g + half * 8;
            size_t rowbase = ((size_t)bh * Sv + m) * Dv;
            #pragma unroll
            for (int nt = 0; nt < 4; nt++) {
                int col = wn + nt * 8 + 2 * tig;
                float v0 = acc[mt][nt][half * 2 + 0];
                float v1 = acc[mt][nt][half * 2 + 1];
                *(float2*)&g_ctx[rowbase + col] =
                    make_float2(__uint_as_float(f2tf(v0)), __uint_as_float(f2tf(v1)));
            }
        }
}

// ---------------- out = ctx(gathered) @ Wo^T + bo (tf32 MMA) ----------------
__global__ __launch_bounds__(256)
void oproj_tf32(const float* __restrict__ Wo, const float* __restrict__ bo,
                float* __restrict__ out) {
    __shared__ unsigned As[128 * SA];
    __shared__ unsigned Bs[128 * SA];
    const int t    = threadIdx.x;
    const int m0   = blockIdx.y * 128;
    const int n0   = blockIdx.x * 128;
    const int w    = t >> 5, lane = t & 31;
    const int g    = lane >> 2, tig = lane & 3;
    const int wm   = (w & 3) * 32, wn = (w >> 2) * 64;
    const int srow = t >> 2, scg = (t & 3) << 2;

    float acc[2][8][4] = {};

    for (int kt = 0; kt < Ev / 16; kt++) {
        const int k0 = kt * 16;
        #pragma unroll
        for (int r = 0; r < 2; r++) {
            int row = srow + r * 64;
            int m = m0 + row;
            int b = m >> 11, s = m & (Sv - 1);
            int k = k0 + scg;
            int h = k >> 6, d = k & 63;
            float4 xa = *(const float4*)(g_ctx + ((size_t)(b * Hv + h) * Sv + s) * Dv + d);
            As[row * SA + scg + 0] = __float_as_uint(xa.x);
            As[row * SA + scg + 1] = __float_as_uint(xa.y);
            As[row * SA + scg + 2] = __float_as_uint(xa.z);
            As[row * SA + scg + 3] = __float_as_uint(xa.w);
            float4 wa = *(const float4*)(Wo + (size_t)(n0 + row) * Ev + k0 + scg);
            Bs[row * SA + scg + 0] = f2tf(wa.x); Bs[row * SA + scg + 1] = f2tf(wa.y);
            Bs[row * SA + scg + 2] = f2tf(wa.z); Bs[row * SA + scg + 3] = f2tf(wa.w);
        }
        __syncthreads();
        #pragma unroll
        for (int ks = 0; ks < 2; ks++) {
            const int kk = ks * 8;
            unsigned a[2][4], b[8][2];
            #pragma unroll
            for (int mt = 0; mt < 2; mt++) {
                int r = wm + mt * 16 + g;
                a[mt][0] = As[r * SA + kk + tig];
                a[mt][1] = As[(r + 8) * SA + kk + tig];
                a[mt][2] = As[r * SA + kk + tig + 4];
                a[mt][3] = As[(r + 8) * SA + kk + tig + 4];
            }
            #pragma unroll
            for (int nt = 0; nt < 8; nt++) {
                int c = wn + nt * 8 + g;
                b[nt][0] = Bs[c * SA + kk + tig];
                b[nt][1] = Bs[c * SA + kk + tig + 4];
            }
            #pragma unroll
            for (int mt = 0; mt < 2; mt++)
                #pragma unroll
                for (int nt = 0; nt < 8; nt++)
                    mma8(acc[mt][nt], a[mt], b[nt]);
        }
        __syncthreads();
    }

    #pragma unroll
    for (int mt = 0; mt < 2; mt++)
        #pragma unroll
        for (int half = 0; half < 2; half++) {
            int m = m0 + wm + mt * 16 + g + half * 8;
            #pragma unroll
            for (int nt = 0; nt < 8; nt++) {
                int col = n0 + wn + nt * 8 + 2 * tig;
                float v0 = acc[mt][nt][half * 2 + 0] + bo[col];
                float v1 = acc[mt][nt][half * 2 + 1] + bo[col + 1];
                *(float2*)&out[(size_t)m * Ev + col] = make_float2(v0, v1);
            }
        }
}

// ---------------- launch -----------------------------------------------------
extern "C" void kernel_launch(void* const* d_in, const int* in_sizes, int n_in,
                              void* d_out, int out_size) {
    const float* query     = (const float*)d_in[0];
    const float* key       = (const float*)d_in[1];
    const float* value     = (const float*)d_in[2];
    const float* task_bias = (const float*)d_in[3];
    const int*   mask      = (const int*)  d_in[4];
    const float* Wq  = (const float*)d_in[5];  const float* bq  = (const float*)d_in[6];
    const float* Wk  = (const float*)d_in[7];  const float* bk  = (const float*)d_in[8];
    const float* Wv  = (const float*)d_in[9];  const float* bv  = (const float*)d_in[10];
    const float* Wtb = (const float*)d_in[11]; const float* btb = (const float*)d_in[12];
    const float* Wo  = (const float*)d_in[13]; const float* bo  = (const float*)d_in[14];

    float* outp = (float*)d_out;
    float* attn = outp + (size_t)Bv * Sv * Ev;

    tb_kernel<<<1, 32>>>(task_bias, Wtb, btb);

    dim3 pg(Ev / 128, Mv / 128);                 // (6, 32)
    proj_tf32<<<pg, 256>>>(query, Wq, bq, 0);
    proj_tf32<<<pg, 256>>>(key,   Wk, bk, 1);
    proj_tf32<<<pg, 256>>>(value, Wv, bv, 2);

    dim3 sg(Sv / 128, Sv / 128, BHv);            // (16, 16, 24)
    scores_tf32<<<sg, 256>>>(attn);

    softmax_kernel<<<BHv * Sv, 256>>>(attn, mask);

    dim3 ag(1, Sv / 128, BHv);                   // (1, 16, 24)
    av_tf32<<<ag, 256>>>(attn);

    oproj_tf32<<<pg, 256>>>(Wo, bo, outp);
}